// round 6
// baseline (speedup 1.0000x reference)
#include <cuda_runtime.h>
#include <cuda_bf16.h>
#include <math_constants.h>

// ---------------------------------------------------------------------------
// CrossAttention: out = softmax((xWq)(ctxWk)^T * scale - (1-mask)*1e6) (ctxWv) Wout + bout
// NOTE: the -1e6 penalty is a per-row constant over the softmax axis, so it is
// a mathematical no-op — but in fp32 it QUANTIZES masked-row logits to the
// 0.0625 grid (ulp of 1e6). We must reproduce that rounding to match the
// reference within 1e-3.
// B=2, N=M=2048, D=1024, H=16, Dh=64, inner=1024
// ---------------------------------------------------------------------------

#define BATCH 2
#define SEQ   2048
#define DMODEL 1024
#define HEADS 16
#define DHEAD 64
#define INNER 1024
#define ROWS  (BATCH * SEQ)       // 4096
#define ATT_SCALE 0.125f          // 64^-0.5
#define MASK_NEG 1000000.0f

// Scratch (static device allocations only, per harness rules)
__device__ float g_q [ROWS * INNER];        // 16 MB
__device__ float g_kv[ROWS * 2 * INNER];    // 32 MB
__device__ float g_ao[ROWS * INNER];        // 16 MB

// ---------------------------------------------------------------------------
// SGEMM: C[M,N] = A[M,K] @ B[K,N] (+bias). Row-major. M,N multiples of 128,
// K multiple of 8. 128x128 block tile, BK=8, 8x8 per thread, 256 threads.
// ---------------------------------------------------------------------------
__global__ __launch_bounds__(256) void sgemm128(
    const float* __restrict__ A, const float* __restrict__ B,
    float* __restrict__ C, int M, int N, int K,
    const float* __restrict__ bias)
{
    __shared__ float As[8][132];   // transposed A tile, padded
    __shared__ float Bs[8][128];

    const int tid = threadIdx.x;
    const int tx = tid & 15;        // col group
    const int ty = tid >> 4;        // row group
    const int row0 = blockIdx.y * 128;
    const int col0 = blockIdx.x * 128;

    // load mapping
    const int arow = tid >> 1;          // 0..127
    const int acol = (tid & 1) * 4;     // 0 or 4
    const int brow = tid >> 5;          // 0..7
    const int bcol = (tid & 31) * 4;    // 0..124

    const float* Aptr = A + (size_t)(row0 + arow) * K + acol;
    const float* Bptr = B + (size_t)brow * N + col0 + bcol;

    float acc[8][8];
    #pragma unroll
    for (int i = 0; i < 8; i++)
        #pragma unroll
        for (int j = 0; j < 8; j++) acc[i][j] = 0.f;

    for (int k0 = 0; k0 < K; k0 += 8) {
        float4 av = *reinterpret_cast<const float4*>(Aptr + k0);
        float4 bv = *reinterpret_cast<const float4*>(Bptr + (size_t)k0 * N);
        __syncthreads();
        As[acol + 0][arow] = av.x;
        As[acol + 1][arow] = av.y;
        As[acol + 2][arow] = av.z;
        As[acol + 3][arow] = av.w;
        *reinterpret_cast<float4*>(&Bs[brow][bcol]) = bv;
        __syncthreads();
        #pragma unroll
        for (int k = 0; k < 8; k++) {
            float a[8], b[8];
            #pragma unroll
            for (int i = 0; i < 8; i++) a[i] = As[k][ty + i * 16];
            #pragma unroll
            for (int j = 0; j < 8; j++) b[j] = Bs[k][tx + j * 16];
            #pragma unroll
            for (int i = 0; i < 8; i++)
                #pragma unroll
                for (int j = 0; j < 8; j++) acc[i][j] = fmaf(a[i], b[j], acc[i][j]);
        }
    }

    #pragma unroll
    for (int i = 0; i < 8; i++) {
        const int r = row0 + ty + i * 16;
        #pragma unroll
        for (int j = 0; j < 8; j++) {
            const int c = col0 + tx + j * 16;
            float v = acc[i][j];
            if (bias) v += bias[c];
            C[(size_t)r * N + c] = v;
        }
    }
}

// ---------------------------------------------------------------------------
// Fused flash attention (fp32). One block: 64 query rows of one (b,h).
// 256 threads, 4x4 register micro-tiles over 64x64 tiles, online softmax.
// Masked rows: logits quantized via fp32 subtraction of 1e6 (match reference).
// ---------------------------------------------------------------------------
#define QT_OFF   0
#define KT_OFF   (64 * 65)
#define ST_OFF   (2 * 64 * 65)
#define VS_OFF   (3 * 64 * 65)
#define RC_OFF   (3 * 64 * 65 + 64 * 64)
#define RL_OFF   (RC_OFF + 64)
#define ATT_SMEM ((RL_OFF + 64) * 4)

__global__ __launch_bounds__(256) void attn_kernel(
    const float* __restrict__ q, const float* __restrict__ kv,
    const int* __restrict__ mask, float* __restrict__ ao)
{
    extern __shared__ float sm[];
    float* Qt = sm + QT_OFF;
    float* Kt = sm + KT_OFF;
    float* St = sm + ST_OFF;
    float* Vs = sm + VS_OFF;
    float* rcorr = sm + RC_OFF;
    float* rl = sm + RL_OFF;

    const int bh = blockIdx.y;
    const int b = bh >> 4;
    const int h = bh & 15;
    const int n0 = blockIdx.x * 64;
    const int tid = threadIdx.x;
    const int tx = tid & 15;
    const int ty = tid >> 4;

    const float* qbase = q + ((size_t)(b * SEQ + n0)) * INNER + h * DHEAD;
    const float* kbase = kv + (size_t)b * SEQ * (2 * INNER) + h * DHEAD;
    const float* vbase = kbase + INNER;

    // Load Q tile, pre-scaled, transposed: Qt[d][r]
    #pragma unroll
    for (int t = 0; t < 16; t++) {
        int e = tid + t * 256;
        int r = e >> 6, d = e & 63;
        Qt[d * 65 + r] = qbase[(size_t)r * INNER + d] * ATT_SCALE;
    }

    float acc[4][4];
    #pragma unroll
    for (int i = 0; i < 4; i++)
        #pragma unroll
        for (int j = 0; j < 4; j++) acc[i][j] = 0.f;

    float m_prev = -CUDART_INF_F;
    float l_run = 0.f;   // valid for tid < 64
    // Per-query-row mask penalty (reproduces reference fp32 rounding)
    float pen = 0.f;
    if (tid < 64)
        pen = (1.0f - (float)mask[b * SEQ + n0 + tid]) * MASK_NEG;

    for (int m0 = 0; m0 < SEQ; m0 += 64) {
        __syncthreads();   // Q ready (iter 0) / prev PV done reading Kt,Vs,St
        #pragma unroll
        for (int t = 0; t < 16; t++) {
            int e = tid + t * 256;
            int r = e >> 6, d = e & 63;
            const size_t off = (size_t)(m0 + r) * (2 * INNER) + d;
            Kt[d * 65 + r] = kbase[off];
            Vs[r * 64 + d] = vbase[off];
        }
        __syncthreads();

        // S[r][c] = sum_d Q[r][d] * K[c][d]  (Q pre-scaled)
        float s[4][4];
        #pragma unroll
        for (int i = 0; i < 4; i++)
            #pragma unroll
            for (int j = 0; j < 4; j++) s[i][j] = 0.f;
        #pragma unroll 4
        for (int d = 0; d < 64; d++) {
            float a[4], bb[4];
            #pragma unroll
            for (int i = 0; i < 4; i++) a[i] = Qt[d * 65 + ty + i * 16];
            #pragma unroll
            for (int j = 0; j < 4; j++) bb[j] = Kt[d * 65 + tx + j * 16];
            #pragma unroll
            for (int i = 0; i < 4; i++)
                #pragma unroll
                for (int j = 0; j < 4; j++) s[i][j] = fmaf(a[i], bb[j], s[i][j]);
        }
        // store transposed: St[c][r]
        #pragma unroll
        for (int i = 0; i < 4; i++)
            #pragma unroll
            for (int j = 0; j < 4; j++)
                St[(tx + j * 16) * 65 + (ty + i * 16)] = s[i][j];
        __syncthreads();

        // Online softmax: thread r (< 64) owns query row r.
        // se = s - pen performed in fp32: for masked rows this quantizes the
        // logit to the 0.0625 grid exactly like the reference's (dots - 1e6).
        if (tid < 64) {
            const int r = tid;
            float mt = -CUDART_INF_F;
            #pragma unroll 8
            for (int jj = 0; jj < 64; jj++) {
                float se = St[jj * 65 + r] - pen;
                mt = fmaxf(mt, se);
            }
            const float m_new = fmaxf(m_prev, mt);
            const float corr = __expf(m_prev - m_new);
            float sum = 0.f;
            #pragma unroll 8
            for (int jj = 0; jj < 64; jj++) {
                float se = St[jj * 65 + r] - pen;
                float p = __expf(se - m_new);
                St[jj * 65 + r] = p;
                sum += p;
            }
            l_run = l_run * corr + sum;
            m_prev = m_new;
            rcorr[r] = corr;
        }
        __syncthreads();

        // Rescale accumulator, then O += P @ V
        float cr[4];
        #pragma unroll
        for (int i = 0; i < 4; i++) cr[i] = rcorr[ty + i * 16];
        #pragma unroll
        for (int i = 0; i < 4; i++)
            #pragma unroll
            for (int j = 0; j < 4; j++) acc[i][j] *= cr[i];

        #pragma unroll 4
        for (int kk = 0; kk < 64; kk++) {
            float a[4], bb[4];
            #pragma unroll
            for (int i = 0; i < 4; i++) a[i] = St[kk * 65 + ty + i * 16];
            #pragma unroll
            for (int j = 0; j < 4; j++) bb[j] = Vs[kk * 64 + tx + j * 16];
            #pragma unroll
            for (int i = 0; i < 4; i++)
                #pragma unroll
                for (int j = 0; j < 4; j++) acc[i][j] = fmaf(a[i], bb[j], acc[i][j]);
        }
    }

    if (tid < 64) rl[tid] = l_run;
    __syncthreads();

    float inv[4];
    #pragma unroll
    for (int i = 0; i < 4; i++) inv[i] = 1.f / rl[ty + i * 16];

    float* obase = ao + ((size_t)(b * SEQ + n0)) * INNER + h * DHEAD;
    #pragma unroll
    for (int i = 0; i < 4; i++)
        #pragma unroll
        for (int j = 0; j < 4; j++)
            obase[(size_t)(ty + i * 16) * INNER + (tx + j * 16)] = acc[i][j] * inv[i];
}

// ---------------------------------------------------------------------------
extern "C" void kernel_launch(void* const* d_in, const int* in_sizes, int n_in,
                              void* d_out, int out_size)
{
    const float* x    = (const float*)d_in[0];
    const float* ctx  = (const float*)d_in[1];
    const int*   mask = (const int*)d_in[2];
    const float* Wq   = (const float*)d_in[3];
    const float* Wkv  = (const float*)d_in[4];
    const float* Wout = (const float*)d_in[5];
    const float* bout = (const float*)d_in[6];
    float* out = (float*)d_out;

    float *q_ptr, *kv_ptr, *ao_ptr;
    cudaGetSymbolAddress((void**)&q_ptr,  g_q);
    cudaGetSymbolAddress((void**)&kv_ptr, g_kv);
    cudaGetSymbolAddress((void**)&ao_ptr, g_ao);

    cudaFuncSetAttribute(attn_kernel,
                         cudaFuncAttributeMaxDynamicSharedMemorySize, ATT_SMEM);

    // q = x @ Wq            [4096,1024] x [1024,1024]
    sgemm128<<<dim3(INNER / 128, ROWS / 128), 256>>>(
        x, Wq, q_ptr, ROWS, INNER, DMODEL, nullptr);
    // kv = context @ Wkv    [4096,1024] x [1024,2048]
    sgemm128<<<dim3(2 * INNER / 128, ROWS / 128), 256>>>(
        ctx, Wkv, kv_ptr, ROWS, 2 * INNER, DMODEL, nullptr);
    // fused attention
    attn_kernel<<<dim3(SEQ / 64, BATCH * HEADS), 256, ATT_SMEM>>>(
        q_ptr, kv_ptr, mask, ao_ptr);
    // out = ao @ Wout + bout
    sgemm128<<<dim3(DMODEL / 128, ROWS / 128), 256>>>(
        ao_ptr, Wout, out, ROWS, DMODEL, INNER, bout);
}

// round 7
// speedup vs baseline: 1.7065x; 1.7065x over previous
#include <cuda_runtime.h>
#include <cuda_bf16.h>
#include <math_constants.h>

// ---------------------------------------------------------------------------
// CrossAttention: out = softmax((xWq)(ctxWk)^T * scale - (1-mask)*1e6) (ctxWv) Wout + bout
// The -1e6 penalty is a per-row constant over the softmax axis (mathematical
// no-op) but in fp32 it QUANTIZES masked-row logits to the 0.0625 grid (ulp of
// 1e6). We reproduce that rounding exactly (se = s - pen in fp32).
// B=2, N=M=2048, D=1024, H=16, Dh=64, inner=1024
// ---------------------------------------------------------------------------

#define BATCH 2
#define SEQ   2048
#define DMODEL 1024
#define HEADS 16
#define DHEAD 64
#define INNER 1024
#define ROWS  (BATCH * SEQ)       // 4096
#define ATT_SCALE 0.125f          // 64^-0.5
#define MASK_NEG 1000000.0f

// Scratch (static device allocations only, per harness rules)
__device__ float g_q [ROWS * INNER];        // 16 MB
__device__ float g_kv[ROWS * 2 * INNER];    // 32 MB
__device__ float g_ao[ROWS * INNER];        // 16 MB

// ---------------------------------------------------------------------------
// SGEMM: C[M,N] = A[M,K] @ B[K,N] (+bias). Row-major. M,N multiples of 128,
// K multiple of 8. 128x128 tile, BK=8, 8x8/thread, 256 threads.
// Double-buffered smem: one __syncthreads per K-step, LDGs issued ahead.
// ---------------------------------------------------------------------------
__global__ __launch_bounds__(256) void sgemm128(
    const float* __restrict__ A, const float* __restrict__ B,
    float* __restrict__ C, int M, int N, int K,
    const float* __restrict__ bias)
{
    __shared__ float As[2][8][132];   // transposed A tile, padded
    __shared__ float Bs[2][8][128];

    const int tid = threadIdx.x;
    const int tx = tid & 15;        // col group
    const int ty = tid >> 4;        // row group
    const int row0 = blockIdx.y * 128;
    const int col0 = blockIdx.x * 128;

    const int arow = tid >> 1;          // 0..127
    const int acol = (tid & 1) * 4;     // 0 or 4
    const int brow = tid >> 5;          // 0..7
    const int bcol = (tid & 31) * 4;    // 0..124

    const float* Aptr = A + (size_t)(row0 + arow) * K + acol;
    const float* Bptr = B + (size_t)brow * N + col0 + bcol;

    float acc[8][8];
    #pragma unroll
    for (int i = 0; i < 8; i++)
        #pragma unroll
        for (int j = 0; j < 8; j++) acc[i][j] = 0.f;

    // prologue: tile 0 -> buffer 0
    {
        float4 av = *reinterpret_cast<const float4*>(Aptr);
        float4 bv = *reinterpret_cast<const float4*>(Bptr);
        As[0][acol + 0][arow] = av.x;
        As[0][acol + 1][arow] = av.y;
        As[0][acol + 2][arow] = av.z;
        As[0][acol + 3][arow] = av.w;
        *reinterpret_cast<float4*>(&Bs[0][brow][bcol]) = bv;
    }
    __syncthreads();

    int cur = 0;
    for (int k0 = 8; ; k0 += 8) {
        const bool more = (k0 < K);
        float4 av, bv;
        if (more) {
            av = *reinterpret_cast<const float4*>(Aptr + k0);
            bv = *reinterpret_cast<const float4*>(Bptr + (size_t)k0 * N);
        }
        // compute on current buffer
        #pragma unroll
        for (int k = 0; k < 8; k++) {
            float a[8], b[8];
            #pragma unroll
            for (int i = 0; i < 8; i++) a[i] = As[cur][k][ty + i * 16];
            #pragma unroll
            for (int j = 0; j < 8; j++) b[j] = Bs[cur][k][tx + j * 16];
            #pragma unroll
            for (int i = 0; i < 8; i++)
                #pragma unroll
                for (int j = 0; j < 8; j++) acc[i][j] = fmaf(a[i], b[j], acc[i][j]);
        }
        if (!more) break;
        const int nxt = cur ^ 1;
        As[nxt][acol + 0][arow] = av.x;
        As[nxt][acol + 1][arow] = av.y;
        As[nxt][acol + 2][arow] = av.z;
        As[nxt][acol + 3][arow] = av.w;
        *reinterpret_cast<float4*>(&Bs[nxt][brow][bcol]) = bv;
        __syncthreads();
        cur = nxt;
    }

    #pragma unroll
    for (int i = 0; i < 8; i++) {
        const int r = row0 + ty + i * 16;
        #pragma unroll
        for (int j = 0; j < 8; j++) {
            const int c = col0 + tx + j * 16;
            float v = acc[i][j];
            if (bias) v += bias[c];
            C[(size_t)r * N + c] = v;
        }
    }
}

// ---------------------------------------------------------------------------
// Fused flash attention (fp32). One block: 64 query rows of one (b,h).
// 256 threads, 4x4 register micro-tiles over 64x64 tiles.
// Online softmax fully parallel: row reductions via __shfl_xor across the 16
// lanes sharing a row; m/l/corr state replicated per-thread in registers.
// ---------------------------------------------------------------------------
#define QT_OFF   0
#define KT_OFF   (64 * 65)
#define ST_OFF   (2 * 64 * 65)
#define VS_OFF   (3 * 64 * 65)
#define ATT_SMEM ((3 * 64 * 65 + 64 * 64) * 4)

__global__ __launch_bounds__(256) void attn_kernel(
    const float* __restrict__ q, const float* __restrict__ kv,
    const int* __restrict__ mask, float* __restrict__ ao)
{
    extern __shared__ float sm[];
    float* Qt = sm + QT_OFF;
    float* Kt = sm + KT_OFF;
    float* St = sm + ST_OFF;
    float* Vs = sm + VS_OFF;

    const int bh = blockIdx.y;
    const int b = bh >> 4;
    const int h = bh & 15;
    const int n0 = blockIdx.x * 64;
    const int tid = threadIdx.x;
    const int tx = tid & 15;
    const int ty = tid >> 4;

    const float* qbase = q + ((size_t)(b * SEQ + n0)) * INNER + h * DHEAD;
    const float* kbase = kv + (size_t)b * SEQ * (2 * INNER) + h * DHEAD;
    const float* vbase = kbase + INNER;

    // Load Q tile, pre-scaled, transposed: Qt[d][r]
    #pragma unroll
    for (int t = 0; t < 16; t++) {
        int e = tid + t * 256;
        int r = e >> 6, d = e & 63;
        Qt[d * 65 + r] = qbase[(size_t)r * INNER + d] * ATT_SCALE;
    }

    float acc[4][4];
    #pragma unroll
    for (int i = 0; i < 4; i++)
        #pragma unroll
        for (int j = 0; j < 4; j++) acc[i][j] = 0.f;

    // Per-thread softmax state for its 4 rows (replicated across the 16 tx
    // lanes of each row; shuffles keep them consistent).
    float m_prev[4], l_run[4], pen[4];
    #pragma unroll
    for (int i = 0; i < 4; i++) {
        m_prev[i] = -CUDART_INF_F;
        l_run[i] = 0.f;
        pen[i] = (1.0f - (float)mask[b * SEQ + n0 + ty + i * 16]) * MASK_NEG;
    }

    for (int m0 = 0; m0 < SEQ; m0 += 64) {
        __syncthreads();   // Q ready (iter 0) / prev PV done with Kt,Vs,St
        #pragma unroll
        for (int t = 0; t < 16; t++) {
            int e = tid + t * 256;
            int r = e >> 6, d = e & 63;
            const size_t off = (size_t)(m0 + r) * (2 * INNER) + d;
            Kt[d * 65 + r] = kbase[off];
            Vs[r * 64 + d] = vbase[off];
        }
        __syncthreads();

        // S[r][c] = sum_d Q[r][d] * K[c][d]  (Q pre-scaled)
        float s[4][4];
        #pragma unroll
        for (int i = 0; i < 4; i++)
            #pragma unroll
            for (int j = 0; j < 4; j++) s[i][j] = 0.f;
        #pragma unroll 4
        for (int d = 0; d < 64; d++) {
            float a[4], bb[4];
            #pragma unroll
            for (int i = 0; i < 4; i++) a[i] = Qt[d * 65 + ty + i * 16];
            #pragma unroll
            for (int j = 0; j < 4; j++) bb[j] = Kt[d * 65 + tx + j * 16];
            #pragma unroll
            for (int i = 0; i < 4; i++)
                #pragma unroll
                for (int j = 0; j < 4; j++) s[i][j] = fmaf(a[i], bb[j], s[i][j]);
        }

        // Parallel online softmax (registers + shuffles).
        // se = s - pen in fp32: masked rows quantize to the 0.0625 grid,
        // matching the reference's (dots - 1e6).
        #pragma unroll
        for (int i = 0; i < 4; i++) {
            float se[4];
            float mt = -CUDART_INF_F;
            #pragma unroll
            for (int j = 0; j < 4; j++) {
                se[j] = s[i][j] - pen[i];
                mt = fmaxf(mt, se[j]);
            }
            #pragma unroll
            for (int o = 8; o >= 1; o >>= 1)
                mt = fmaxf(mt, __shfl_xor_sync(0xffffffffu, mt, o));
            const float m_new = fmaxf(m_prev[i], mt);
            const float corr = __expf(m_prev[i] - m_new);
            float sum = 0.f;
            #pragma unroll
            for (int j = 0; j < 4; j++) {
                float p = __expf(se[j] - m_new);
                St[(tx + j * 16) * 65 + (ty + i * 16)] = p;   // transposed
                sum += p;
            }
            #pragma unroll
            for (int o = 8; o >= 1; o >>= 1)
                sum += __shfl_xor_sync(0xffffffffu, sum, o);
            l_run[i] = l_run[i] * corr + sum;
            m_prev[i] = m_new;
            #pragma unroll
            for (int j = 0; j < 4; j++) acc[i][j] *= corr;
        }
        __syncthreads();

        // O += P @ V
        #pragma unroll 4
        for (int kk = 0; kk < 64; kk++) {
            float a[4], bb[4];
            #pragma unroll
            for (int i = 0; i < 4; i++) a[i] = St[kk * 65 + ty + i * 16];
            #pragma unroll
            for (int j = 0; j < 4; j++) bb[j] = Vs[kk * 64 + tx + j * 16];
            #pragma unroll
            for (int i = 0; i < 4; i++)
                #pragma unroll
                for (int j = 0; j < 4; j++) acc[i][j] = fmaf(a[i], bb[j], acc[i][j]);
        }
    }

    float* obase = ao + ((size_t)(b * SEQ + n0)) * INNER + h * DHEAD;
    #pragma unroll
    for (int i = 0; i < 4; i++) {
        const float inv = 1.f / l_run[i];
        #pragma unroll
        for (int j = 0; j < 4; j++)
            obase[(size_t)(ty + i * 16) * INNER + (tx + j * 16)] = acc[i][j] * inv;
    }
}

// ---------------------------------------------------------------------------
extern "C" void kernel_launch(void* const* d_in, const int* in_sizes, int n_in,
                              void* d_out, int out_size)
{
    const float* x    = (const float*)d_in[0];
    const float* ctx  = (const float*)d_in[1];
    const int*   mask = (const int*)d_in[2];
    const float* Wq   = (const float*)d_in[3];
    const float* Wkv  = (const float*)d_in[4];
    const float* Wout = (const float*)d_in[5];
    const float* bout = (const float*)d_in[6];
    float* out = (float*)d_out;

    float *q_ptr, *kv_ptr, *ao_ptr;
    cudaGetSymbolAddress((void**)&q_ptr,  g_q);
    cudaGetSymbolAddress((void**)&kv_ptr, g_kv);
    cudaGetSymbolAddress((void**)&ao_ptr, g_ao);

    cudaFuncSetAttribute(attn_kernel,
                         cudaFuncAttributeMaxDynamicSharedMemorySize, ATT_SMEM);

    // q = x @ Wq            [4096,1024] x [1024,1024]
    sgemm128<<<dim3(INNER / 128, ROWS / 128), 256>>>(
        x, Wq, q_ptr, ROWS, INNER, DMODEL, nullptr);
    // kv = context @ Wkv    [4096,1024] x [1024,2048]
    sgemm128<<<dim3(2 * INNER / 128, ROWS / 128), 256>>>(
        ctx, Wkv, kv_ptr, ROWS, 2 * INNER, DMODEL, nullptr);
    // fused attention
    attn_kernel<<<dim3(SEQ / 64, BATCH * HEADS), 256, ATT_SMEM>>>(
        q_ptr, kv_ptr, mask, ao_ptr);
    // out = ao @ Wout + bout
    sgemm128<<<dim3(DMODEL / 128, ROWS / 128), 256>>>(
        ao_ptr, Wout, out, ROWS, DMODEL, INNER, bout);
}

// round 8
// speedup vs baseline: 2.0043x; 1.1746x over previous
#include <cuda_runtime.h>
#include <cuda_bf16.h>
#include <math_constants.h>

// ---------------------------------------------------------------------------
// CrossAttention: out = softmax((xWq)(ctxWk)^T * scale - (1-mask)*1e6) (ctxWv) Wout + bout
// The -1e6 penalty is a per-row constant over the softmax axis (mathematical
// no-op) but in fp32 it QUANTIZES masked-row logits to the 0.0625 grid (ulp of
// 1e6). We reproduce that rounding exactly (se = s - pen in fp32).
// B=2, N=M=2048, D=1024, H=16, Dh=64, inner=1024
// ---------------------------------------------------------------------------

#define BATCH 2
#define SEQ   2048
#define DMODEL 1024
#define HEADS 16
#define DHEAD 64
#define INNER 1024
#define ROWS  (BATCH * SEQ)       // 4096
#define ATT_SCALE 0.125f          // 64^-0.5
#define MASK_NEG 1000000.0f

// Scratch (static device allocations only, per harness rules)
__device__ float g_q [ROWS * INNER];        // 16 MB
__device__ float g_kv[ROWS * 2 * INNER];    // 32 MB
__device__ float g_ao[ROWS * INNER];        // 16 MB

// ---------------------------------------------------------------------------
// SGEMM: C[M,N] = A[M,K] @ B[K,N] (+bias). Row-major. M,N multiples of 128,
// K multiple of 8. 128x128 tile, BK=8, 8x8/thread as 2x2 blocks of 4
// contiguous rows/cols -> all smem traffic is LDS.128 / STG.128.
// Double-buffered smem, one __syncthreads per K-step.
// ---------------------------------------------------------------------------
__global__ __launch_bounds__(256) void sgemm128(
    const float* __restrict__ A, const float* __restrict__ B,
    float* __restrict__ C, int M, int N, int K,
    const float* __restrict__ bias)
{
    __shared__ float As[2][8][132];   // transposed A tile, padded
    __shared__ float Bs[2][8][128];

    const int tid = threadIdx.x;
    const int tx = tid & 15;        // col group: cols tx*4..+3 and 64+tx*4..+3
    const int ty = tid >> 4;        // row group: rows ty*4..+3 and 64+ty*4..+3
    const int row0 = blockIdx.y * 128;
    const int col0 = blockIdx.x * 128;

    const int arow = tid >> 1;          // 0..127
    const int acol = (tid & 1) * 4;     // 0 or 4
    const int brow = tid >> 5;          // 0..7
    const int bcol = (tid & 31) * 4;    // 0..124

    const float* Aptr = A + (size_t)(row0 + arow) * K + acol;
    const float* Bptr = B + (size_t)brow * N + col0 + bcol;

    float acc[8][8];
    #pragma unroll
    for (int i = 0; i < 8; i++)
        #pragma unroll
        for (int j = 0; j < 8; j++) acc[i][j] = 0.f;

    // prologue: tile 0 -> buffer 0
    {
        float4 av = *reinterpret_cast<const float4*>(Aptr);
        float4 bv = *reinterpret_cast<const float4*>(Bptr);
        As[0][acol + 0][arow] = av.x;
        As[0][acol + 1][arow] = av.y;
        As[0][acol + 2][arow] = av.z;
        As[0][acol + 3][arow] = av.w;
        *reinterpret_cast<float4*>(&Bs[0][brow][bcol]) = bv;
    }
    __syncthreads();

    int cur = 0;
    for (int k0 = 8; ; k0 += 8) {
        const bool more = (k0 < K);
        float4 av, bv;
        if (more) {
            av = *reinterpret_cast<const float4*>(Aptr + k0);
            bv = *reinterpret_cast<const float4*>(Bptr + (size_t)k0 * N);
        }
        // compute on current buffer (all vectorized smem reads)
        #pragma unroll
        for (int k = 0; k < 8; k++) {
            float4 a0 = *reinterpret_cast<const float4*>(&As[cur][k][ty * 4]);
            float4 a1 = *reinterpret_cast<const float4*>(&As[cur][k][64 + ty * 4]);
            float4 b0 = *reinterpret_cast<const float4*>(&Bs[cur][k][tx * 4]);
            float4 b1 = *reinterpret_cast<const float4*>(&Bs[cur][k][64 + tx * 4]);
            float a[8] = {a0.x, a0.y, a0.z, a0.w, a1.x, a1.y, a1.z, a1.w};
            float b[8] = {b0.x, b0.y, b0.z, b0.w, b1.x, b1.y, b1.z, b1.w};
            #pragma unroll
            for (int i = 0; i < 8; i++)
                #pragma unroll
                for (int j = 0; j < 8; j++) acc[i][j] = fmaf(a[i], b[j], acc[i][j]);
        }
        if (!more) break;
        const int nxt = cur ^ 1;
        As[nxt][acol + 0][arow] = av.x;
        As[nxt][acol + 1][arow] = av.y;
        As[nxt][acol + 2][arow] = av.z;
        As[nxt][acol + 3][arow] = av.w;
        *reinterpret_cast<float4*>(&Bs[nxt][brow][bcol]) = bv;
        __syncthreads();
        cur = nxt;
    }

    // epilogue: vectorized stores (2 STG.128 per register row)
    float4 bias0 = make_float4(0.f, 0.f, 0.f, 0.f);
    float4 bias1 = bias0;
    if (bias) {
        bias0 = *reinterpret_cast<const float4*>(&bias[col0 + tx * 4]);
        bias1 = *reinterpret_cast<const float4*>(&bias[col0 + 64 + tx * 4]);
    }
    #pragma unroll
    for (int i = 0; i < 8; i++) {
        const int r = row0 + (i < 4 ? ty * 4 + i : 64 + ty * 4 + (i - 4));
        float4 v0 = make_float4(acc[i][0] + bias0.x, acc[i][1] + bias0.y,
                                acc[i][2] + bias0.z, acc[i][3] + bias0.w);
        float4 v1 = make_float4(acc[i][4] + bias1.x, acc[i][5] + bias1.y,
                                acc[i][6] + bias1.z, acc[i][7] + bias1.w);
        *reinterpret_cast<float4*>(&C[(size_t)r * N + col0 + tx * 4]) = v0;
        *reinterpret_cast<float4*>(&C[(size_t)r * N + col0 + 64 + tx * 4]) = v1;
    }
}

// ---------------------------------------------------------------------------
// Fused flash attention (fp32). One block: 64 query rows of one (b,h).
// 256 threads, contiguous 4x4 micro-tiles (rows ty*4+i, cols tx*4+j) so all
// hot smem traffic is LDS.128 / broadcast. Online softmax via register
// shuffles across the 16 lanes sharing a row.
// Strides padded to 68 floats for 16B alignment.
// ---------------------------------------------------------------------------
#define AT_STRIDE 68
#define QT_OFF   0
#define KT_OFF   (64 * AT_STRIDE)
#define ST_OFF   (2 * 64 * AT_STRIDE)
#define VS_OFF   (3 * 64 * AT_STRIDE)
#define ATT_SMEM (4 * 64 * AT_STRIDE * 4)

__global__ __launch_bounds__(256) void attn_kernel(
    const float* __restrict__ q, const float* __restrict__ kv,
    const int* __restrict__ mask, float* __restrict__ ao)
{
    extern __shared__ float sm[];
    float* Qt = sm + QT_OFF;   // [d][r]
    float* Kt = sm + KT_OFF;   // [d][c]
    float* St = sm + ST_OFF;   // [r][c]  (P, non-transposed)
    float* Vs = sm + VS_OFF;   // [k][c]

    const int bh = blockIdx.y;
    const int b = bh >> 4;
    const int h = bh & 15;
    const int n0 = blockIdx.x * 64;
    const int tid = threadIdx.x;
    const int tx = tid & 15;
    const int ty = tid >> 4;
    const int lr = tid >> 4;        // load row helper (0..15)
    const int f4 = tid & 15;        // load float4-column helper

    const float* qbase = q + ((size_t)(b * SEQ + n0)) * INNER + h * DHEAD;
    const float* kbase = kv + (size_t)b * SEQ * (2 * INNER) + h * DHEAD;
    const float* vbase = kbase + INNER;

    // Load Q tile (float4 gmem), pre-scaled, transposed: Qt[d][r]
    #pragma unroll
    for (int t = 0; t < 4; t++) {
        int r = lr + t * 16;
        float4 qv = *reinterpret_cast<const float4*>(&qbase[(size_t)r * INNER + f4 * 4]);
        Qt[(f4 * 4 + 0) * AT_STRIDE + r] = qv.x * ATT_SCALE;
        Qt[(f4 * 4 + 1) * AT_STRIDE + r] = qv.y * ATT_SCALE;
        Qt[(f4 * 4 + 2) * AT_STRIDE + r] = qv.z * ATT_SCALE;
        Qt[(f4 * 4 + 3) * AT_STRIDE + r] = qv.w * ATT_SCALE;
    }

    float acc[4][4];
    #pragma unroll
    for (int i = 0; i < 4; i++)
        #pragma unroll
        for (int j = 0; j < 4; j++) acc[i][j] = 0.f;

    // Per-thread softmax state for its 4 rows (replicated across the 16 tx
    // lanes of each row; shuffles keep them consistent).
    float m_prev[4], l_run[4], pen[4];
    #pragma unroll
    for (int i = 0; i < 4; i++) {
        m_prev[i] = -CUDART_INF_F;
        l_run[i] = 0.f;
        pen[i] = (1.0f - (float)mask[b * SEQ + n0 + ty * 4 + i]) * MASK_NEG;
    }

    for (int m0 = 0; m0 < SEQ; m0 += 64) {
        __syncthreads();   // Q ready (iter 0) / prev PV done with Kt,Vs,St
        #pragma unroll
        for (int t = 0; t < 4; t++) {
            int r = lr + t * 16;
            const size_t off = (size_t)(m0 + r) * (2 * INNER) + f4 * 4;
            float4 kk = *reinterpret_cast<const float4*>(&kbase[off]);
            float4 vv = *reinterpret_cast<const float4*>(&vbase[off]);
            Kt[(f4 * 4 + 0) * AT_STRIDE + r] = kk.x;
            Kt[(f4 * 4 + 1) * AT_STRIDE + r] = kk.y;
            Kt[(f4 * 4 + 2) * AT_STRIDE + r] = kk.z;
            Kt[(f4 * 4 + 3) * AT_STRIDE + r] = kk.w;
            *reinterpret_cast<float4*>(&Vs[r * AT_STRIDE + f4 * 4]) = vv;
        }
        __syncthreads();

        // S[r][c] = sum_d Q[r][d] * K[c][d]  (Q pre-scaled)
        float s[4][4];
        #pragma unroll
        for (int i = 0; i < 4; i++)
            #pragma unroll
            for (int j = 0; j < 4; j++) s[i][j] = 0.f;
        #pragma unroll 8
        for (int d = 0; d < 64; d++) {
            float4 av = *reinterpret_cast<const float4*>(&Qt[d * AT_STRIDE + ty * 4]);
            float4 bv = *reinterpret_cast<const float4*>(&Kt[d * AT_STRIDE + tx * 4]);
            float a[4] = {av.x, av.y, av.z, av.w};
            float bb[4] = {bv.x, bv.y, bv.z, bv.w};
            #pragma unroll
            for (int i = 0; i < 4; i++)
                #pragma unroll
                for (int j = 0; j < 4; j++) s[i][j] = fmaf(a[i], bb[j], s[i][j]);
        }

        // Parallel online softmax (registers + shuffles).
        // se = s - pen in fp32: masked rows quantize to the 0.0625 grid,
        // matching the reference's (dots - 1e6).
        #pragma unroll
        for (int i = 0; i < 4; i++) {
            float se[4];
            float mt = -CUDART_INF_F;
            #pragma unroll
            for (int j = 0; j < 4; j++) {
                se[j] = s[i][j] - pen[i];
                mt = fmaxf(mt, se[j]);
            }
            #pragma unroll
            for (int o = 8; o >= 1; o >>= 1)
                mt = fmaxf(mt, __shfl_xor_sync(0xffffffffu, mt, o));
            const float m_new = fmaxf(m_prev[i], mt);
            const float corr = __expf(m_prev[i] - m_new);
            float p0 = __expf(se[0] - m_new);
            float p1 = __expf(se[1] - m_new);
            float p2 = __expf(se[2] - m_new);
            float p3 = __expf(se[3] - m_new);
            *reinterpret_cast<float4*>(&St[(ty * 4 + i) * AT_STRIDE + tx * 4]) =
                make_float4(p0, p1, p2, p3);
            float sum = p0 + p1 + p2 + p3;
            #pragma unroll
            for (int o = 8; o >= 1; o >>= 1)
                sum += __shfl_xor_sync(0xffffffffu, sum, o);
            l_run[i] = l_run[i] * corr + sum;
            m_prev[i] = m_new;
            #pragma unroll
            for (int j = 0; j < 4; j++) acc[i][j] *= corr;
        }
        __syncthreads();

        // O += P @ V   (P rows broadcast, V via LDS.128)
        #pragma unroll 8
        for (int kk = 0; kk < 64; kk++) {
            float a[4];
            #pragma unroll
            for (int i = 0; i < 4; i++) a[i] = St[(ty * 4 + i) * AT_STRIDE + kk];
            float4 bv = *reinterpret_cast<const float4*>(&Vs[kk * AT_STRIDE + tx * 4]);
            float bb[4] = {bv.x, bv.y, bv.z, bv.w};
            #pragma unroll
            for (int i = 0; i < 4; i++)
                #pragma unroll
                for (int j = 0; j < 4; j++) acc[i][j] = fmaf(a[i], bb[j], acc[i][j]);
        }
    }

    float* obase = ao + ((size_t)(b * SEQ + n0)) * INNER + h * DHEAD;
    #pragma unroll
    for (int i = 0; i < 4; i++) {
        const float inv = 1.f / l_run[i];
        *reinterpret_cast<float4*>(&obase[(size_t)(ty * 4 + i) * INNER + tx * 4]) =
            make_float4(acc[i][0] * inv, acc[i][1] * inv,
                        acc[i][2] * inv, acc[i][3] * inv);
    }
}

// ---------------------------------------------------------------------------
extern "C" void kernel_launch(void* const* d_in, const int* in_sizes, int n_in,
                              void* d_out, int out_size)
{
    const float* x    = (const float*)d_in[0];
    const float* ctx  = (const float*)d_in[1];
    const int*   mask = (const int*)d_in[2];
    const float* Wq   = (const float*)d_in[3];
    const float* Wkv  = (const float*)d_in[4];
    const float* Wout = (const float*)d_in[5];
    const float* bout = (const float*)d_in[6];
    float* out = (float*)d_out;

    float *q_ptr, *kv_ptr, *ao_ptr;
    cudaGetSymbolAddress((void**)&q_ptr,  g_q);
    cudaGetSymbolAddress((void**)&kv_ptr, g_kv);
    cudaGetSymbolAddress((void**)&ao_ptr, g_ao);

    cudaFuncSetAttribute(attn_kernel,
                         cudaFuncAttributeMaxDynamicSharedMemorySize, ATT_SMEM);

    // q = x @ Wq            [4096,1024] x [1024,1024]
    sgemm128<<<dim3(INNER / 128, ROWS / 128), 256>>>(
        x, Wq, q_ptr, ROWS, INNER, DMODEL, nullptr);
    // kv = context @ Wkv    [4096,1024] x [1024,2048]
    sgemm128<<<dim3(2 * INNER / 128, ROWS / 128), 256>>>(
        ctx, Wkv, kv_ptr, ROWS, 2 * INNER, DMODEL, nullptr);
    // fused attention
    attn_kernel<<<dim3(SEQ / 64, BATCH * HEADS), 256, ATT_SMEM>>>(
        q_ptr, kv_ptr, mask, ao_ptr);
    // out = ao @ Wout + bout
    sgemm128<<<dim3(DMODEL / 128, ROWS / 128), 256>>>(
        ao_ptr, Wout, out, ROWS, DMODEL, INNER, bout);
}